// round 15
// baseline (speedup 1.0000x reference)
#include <cuda_runtime.h>
#include <math.h>
#include <stdint.h>

typedef unsigned long long ull;

#define BATCH 128
#define TLEN 4096

// ---------------- scratch: static device globals (no allocations) ----------------
__device__ float g_featsA[(size_t)BATCH * TLEN * 16];  // [B][T][16] tf32-rounded, c>=10 zero
__device__ float g_h1[(size_t)BATCH * TLEN * 64];      // [B][T][64] tf32-rounded gelu(conv1)
__device__ float g_scr[4][(size_t)BATCH * TLEN];       // hcv/anv/scv (sentinel -1) + otv
__device__ float g_rule[(size_t)BATCH * TLEN];         // [B,T]
__device__ float g_lr[(size_t)BATCH * TLEN];           // [B,T] sigmoid(conv3)*mask
__device__ float g_wf2[40 * 512];                      // conv2 B fragments [ks][nt][lane][2]
__device__ float g_wf1[10 * 512];                      // conv1 B fragments

// ---------------- helpers ----------------
__device__ __forceinline__ float gelu_exact(float x) {
    return 0.5f * x * (1.0f + erff(x * 0.70710678118654752440f));
}
__device__ __forceinline__ float sigmoidf(float x) { return 1.0f / (1.0f + expf(-x)); }
__device__ __forceinline__ float safenorm2(float x, float y) {
    float s = x * x + y * y;
    return s > 0.0f ? sqrtf(s) : 0.0f;
}
__device__ __forceinline__ float totf32(float x) {
    float r;
    asm("cvt.rna.tf32.f32 %0,%1;" : "=f"(r) : "f"(x));
    return r;
}
// m16n8k8 tf32 MMA (HMMA path, valid on plain sm_103 target)
__device__ __forceinline__ void mma8(float* d, const uint32_t* a, uint2 b) {
    asm volatile(
        "mma.sync.aligned.m16n8k8.row.col.f32.tf32.tf32.f32 "
        "{%0,%1,%2,%3},{%4,%5,%6,%7},{%8,%9},{%0,%1,%2,%3};"
        : "+f"(d[0]), "+f"(d[1]), "+f"(d[2]), "+f"(d[3])
        : "r"(a[0]), "r"(a[1]), "r"(a[2]), "r"(a[3]), "r"(b.x), "r"(b.y));
}

// ---------------- block reductions (blockDim.x == 1024) ----------------
__device__ float blockReduceSum1024(float v) {
    __shared__ float red[32];
    __syncthreads();
#pragma unroll
    for (int o = 16; o > 0; o >>= 1) v += __shfl_xor_sync(0xffffffffu, v, o);
    if ((threadIdx.x & 31) == 0) red[threadIdx.x >> 5] = v;
    __syncthreads();
    if (threadIdx.x == 0) {
        float s = 0.0f;
        for (int i = 0; i < 32; i++) s += red[i];
        red[0] = s;
    }
    __syncthreads();
    float r = red[0];
    __syncthreads();
    return r;
}
__device__ float blockReduceMax1024(float v) {
    __shared__ float red[32];
    __syncthreads();
#pragma unroll
    for (int o = 16; o > 0; o >>= 1) v = fmaxf(v, __shfl_xor_sync(0xffffffffu, v, o));
    if ((threadIdx.x & 31) == 0) red[threadIdx.x >> 5] = v;
    __syncthreads();
    if (threadIdx.x == 0) {
        float s = red[0];
        for (int i = 1; i < 32; i++) s = fmaxf(s, red[i]);
        red[0] = s;
    }
    __syncthreads();
    float r = red[0];
    __syncthreads();
    return r;
}

// ---------------- exact k-th smallest: 3 concurrent MSD radix selects (1024 thr) -------
__device__ void radix_select3(const float* s0, const float* s1, const float* s2, int k,
                              float* kth) {
    __shared__ unsigned hist[3][256];
    __shared__ unsigned sh_pref[3];
    __shared__ int sh_k[3];
    unsigned pref[3] = {0u, 0u, 0u};
    int kk[3] = {k, k, k};
    int tid = threadIdx.x;
    for (int shift = 24; shift >= 0; shift -= 8) {
        __syncthreads();
        if (tid < 256) { hist[0][tid] = 0u; hist[1][tid] = 0u; hist[2][tid] = 0u; }
        __syncthreads();
        unsigned pmask = (shift == 24) ? 0u : (0xFFFFFFFFu << (shift + 8));
#pragma unroll
        for (int j = 0; j < 4; j++) {
            int t = j * 1024 + tid;
            float v0 = s0[t], v1 = s1[t], v2 = s2[t];
            unsigned k0 = (v0 >= 0.0f) ? __float_as_uint(v0) : 0xFFFFFFFFu;
            unsigned k1 = (v1 >= 0.0f) ? __float_as_uint(v1) : 0xFFFFFFFFu;
            unsigned k2 = (v2 >= 0.0f) ? __float_as_uint(v2) : 0xFFFFFFFFu;
            if ((k0 & pmask) == (pref[0] & pmask)) atomicAdd(&hist[0][(k0 >> shift) & 255u], 1u);
            if ((k1 & pmask) == (pref[1] & pmask)) atomicAdd(&hist[1][(k1 >> shift) & 255u], 1u);
            if ((k2 & pmask) == (pref[2] & pmask)) atomicAdd(&hist[2][(k2 >> shift) & 255u], 1u);
        }
        __syncthreads();
        if (tid < 96) {
            int w = tid >> 5, ln = tid & 31;
            unsigned loc[8], tot = 0u;
#pragma unroll
            for (int j = 0; j < 8; j++) { loc[j] = hist[w][ln * 8 + j]; tot += loc[j]; }
            unsigned inc = tot;
#pragma unroll
            for (int o = 1; o < 32; o <<= 1) {
                unsigned v = __shfl_up_sync(0xffffffffu, inc, o);
                if (ln >= o) inc += v;
            }
            unsigned cum = inc - tot;
            int kw = kk[w];
#pragma unroll
            for (int j = 0; j < 8; j++) {
                unsigned nc = cum + loc[j];
                if (cum < (unsigned)kw && (unsigned)kw <= nc) {
                    sh_pref[w] = pref[w] | ((unsigned)(ln * 8 + j) << shift);
                    sh_k[w] = kw - (int)cum;
                }
                cum = nc;
            }
        }
        __syncthreads();
#pragma unroll
        for (int w = 0; w < 3; w++) { pref[w] = sh_pref[w]; kk[w] = sh_k[w]; }
    }
    kth[0] = __uint_as_float(pref[0]);
    kth[1] = __uint_as_float(pref[1]);
    kth[2] = __uint_as_float(pref[2]);
}

__device__ float radix_select(const float* s, int k) {
    __shared__ unsigned hist[256];
    __shared__ unsigned sh_pref;
    __shared__ int sh_k;
    unsigned prefix = 0;
    int tid = threadIdx.x;
    for (int shift = 24; shift >= 0; shift -= 8) {
        __syncthreads();
        if (tid < 256) hist[tid] = 0u;
        __syncthreads();
        unsigned pmask = (shift == 24) ? 0u : (0xFFFFFFFFu << (shift + 8));
#pragma unroll
        for (int j = 0; j < 4; j++) {
            int t = j * 1024 + tid;
            float v = s[t];
            unsigned key = (v >= 0.0f) ? __float_as_uint(v) : 0xFFFFFFFFu;
            if ((key & pmask) == (prefix & pmask))
                atomicAdd(&hist[(key >> shift) & 0xFFu], 1u);
        }
        __syncthreads();
        if (tid < 32) {
            unsigned loc[8], tot = 0u;
#pragma unroll
            for (int j = 0; j < 8; j++) { loc[j] = hist[tid * 8 + j]; tot += loc[j]; }
            unsigned inc = tot;
#pragma unroll
            for (int o = 1; o < 32; o <<= 1) {
                unsigned v = __shfl_up_sync(0xffffffffu, inc, o);
                if (tid >= o) inc += v;
            }
            unsigned cum = inc - tot;
#pragma unroll
            for (int j = 0; j < 8; j++) {
                unsigned nc = cum + loc[j];
                if (cum < (unsigned)k && (unsigned)k <= nc) {
                    sh_pref = prefix | ((unsigned)(tid * 8 + j) << shift);
                    sh_k = k - (int)cum;
                }
                cum = nc;
            }
        }
        __syncthreads();
        prefix = sh_pref;
        k = sh_k;
    }
    return __uint_as_float(prefix);
}

__device__ float fixup_den(float kth, const float* s) {
    float mx = 0.0f;
    int tid = threadIdx.x;
#pragma unroll
    for (int j = 0; j < 4; j++) mx = fmaxf(mx, s[j * 1024 + tid]);
    mx = blockReduceMax1024(mx);
    float scale = fabsf(kth);
    if (scale < 1e-6f) scale = mx;
    return fmaxf(scale, 1e-6f);
}

// ---------------- kernel: per-timestep features (full-chip grid) ----------------
__global__ void __launch_bounds__(256) k_feat(const float* __restrict__ traj,
                                              const float* __restrict__ intervals,
                                              const float* __restrict__ amask,
                                              const float* __restrict__ obs) {
    int b = blockIdx.y;
    int t = blockIdx.x * 256 + threadIdx.x;
    const float* tr = traj + (size_t)b * TLEN * 2;
    const float* iv = intervals + (size_t)b * TLEN;
    const float* ms = amask + (size_t)b * TLEN;
    const float* ob = obs + (size_t)b * TLEN;

    float m0 = ms[t];
    float m1 = (t >= 1) ? ms[t - 1] : 0.0f;
    float m2 = (t >= 2) ? ms[t - 2] : 0.0f;
    bool v0 = m0 > 0.5f, v1 = m1 > 0.5f, v2 = m2 > 0.5f;
    float pm = (v0 && v1) ? 1.0f : 0.0f;
    float pm1 = (v1 && v2) ? 1.0f : 0.0f;
    float x0 = tr[2 * t] * m0, y0 = tr[2 * t + 1] * m0;
    float x1 = 0.0f, y1 = 0.0f, x2 = 0.0f, y2 = 0.0f, i1 = 0.0f, ob1 = 0.0f;
    if (t >= 1) { x1 = tr[2 * t - 2] * m1; y1 = tr[2 * t - 1] * m1; i1 = iv[t - 1]; ob1 = ob[t - 1]; }
    if (t >= 2) { x2 = tr[2 * t - 4] * m2; y2 = tr[2 * t - 3] * m2; }
    float i0 = iv[t], ob0 = ob[t];
    float dt0 = fmaxf(i0, 1e-3f), dt1 = fmaxf(i1, 1e-3f);
    float cdx = (t >= 1) ? (x0 - x1) * pm : 0.0f;
    float cdy = (t >= 1) ? (y0 - y1) * pm : 0.0f;
    float vx = cdx / dt0 * m0, vy = cdy / dt0 * m0;
    float cdx1 = (t >= 2) ? (x1 - x2) * pm1 : 0.0f;
    float cdy1 = (t >= 2) ? (y1 - y2) * pm1 : 0.0f;
    float vx1 = cdx1 / dt1 * m1, vy1 = cdy1 / dt1 * m1;
    float ax = (t >= 1) ? (vx - vx1) * pm / dt0 * m0 : 0.0f;
    float ay = (t >= 1) ? (vy - vy1) * pm / dt0 * m0 : 0.0f;
    float sp = safenorm2(vx, vy) * m0;
    float sp1 = safenorm2(vx1, vy1) * m1;
    float scv = (t >= 1) ? fabsf((sp - sp1) * pm) * m0 : 0.0f;
    float anv = safenorm2(ax, ay) * m0;

    // heading change: wrap(hd - hd1) == atan2(cross, dot) when BOTH velocity vectors
    // are nonzero (one atan2 instead of 3 + sin + cos). Zero-vector cases (sequence
    // starts / gaps, where atan2(0,0)=0 semantics matter) take the exact reference path.
    float wrapped;
    bool z0 = (vx == 0.0f && vy == 0.0f);
    bool z1 = (vx1 == 0.0f && vy1 == 0.0f);
    if (!z0 && !z1) {
        float cr = vy * vx1 - vx * vy1;
        float dp = vx * vx1 + vy * vy1;
        wrapped = atan2f(cr, dp);
    } else {
        float hd = atan2f(vy, vx), hd1 = atan2f(vy1, vx1);
        float dd = hd - hd1;
        wrapped = atan2f(sinf(dd), cosf(dd));
    }
    float hcv = (t >= 1) ? fabsf(wrapped) * pm * m0 : 0.0f;

    float otv = (t >= 1) ? fabsf(ob0 - ob1) * pm : 0.0f;
    otv = fminf(fmaxf(otv, 0.0f), 1.0f);

    // features [B][T][16] tf32-rounded, channels 10..15 zero
    float4* fb = (float4*)(g_featsA + ((size_t)b * TLEN + t) * 16);
    fb[0] = make_float4(totf32(x0), totf32(y0), totf32(vx), totf32(vy));
    fb[1] = make_float4(totf32(ax), totf32(ay), totf32(sp), totf32(hcv));
    fb[2] = make_float4(totf32(i0 * m0), totf32(ob0 * m0), 0.0f, 0.0f);
    fb[3] = make_float4(0.0f, 0.0f, 0.0f, 0.0f);

    size_t off = (size_t)b * TLEN + t;
    g_scr[0][off] = v0 ? hcv : -1.0f;
    g_scr[1][off] = v0 ? anv : -1.0f;
    g_scr[2][off] = v0 ? scv : -1.0f;
    g_scr[3][off] = otv;
}

// ---------------- kernel: build tf32 B-fragment tables in global ----------------
// block 0..39: conv2 k-step; block 40..49: conv1 k-step. 256 threads = [nt(8)][lane(32)].
__global__ void __launch_bounds__(256) k_prepw(const float* __restrict__ w1,
                                               const float* __restrict__ w2) {
    int idx = threadIdx.x;
    int ln = idx & 31;
    int nt = idx >> 5;
    int n = nt * 8 + (ln >> 2);
    if (blockIdx.x < 40) {
        int ks = blockIdx.x;
        int tap = ks >> 3, s = ks & 7;
        int c0 = s * 8 + (ln & 3);
        float v0 = w2[(n * 64 + c0) * 5 + tap];
        float v1 = w2[(n * 64 + c0 + 4) * 5 + tap];
        *(float2*)(g_wf2 + ks * 512 + idx * 2) = make_float2(totf32(v0), totf32(v1));
    } else {
        int ks = blockIdx.x - 40;
        int tap = ks >> 1, s = ks & 1;
        int c0 = s * 8 + (ln & 3);
        float v0 = (c0 < 10) ? w1[(n * 10 + c0) * 5 + tap] : 0.0f;
        float v1 = (c0 + 4 < 10) ? w1[(n * 10 + c0 + 4) * 5 + tap] : 0.0f;
        *(float2*)(g_wf1 + ks * 512 + idx * 2) = make_float2(totf32(v0), totf32(v1));
    }
}

// ---------------- kernel: rule scores (1 CTA per batch row, 1024 threads) ----------
__global__ void __launch_bounds__(1024) k_rule(const float* __restrict__ amask) {
    extern __shared__ float smx[];
    float* sA = smx;
    float* sB = smx + TLEN;
    float* sC = smx + 2 * TLEN;

    int b = blockIdx.x;
    int tid = threadIdx.x;
    const float* ms = amask + (size_t)b * TLEN;
    size_t boff = (size_t)b * TLEN;

    float cnt = 0.0f;
#pragma unroll
    for (int j = 0; j < 4; j++) {
        int t = j * 1024 + tid;
        float a = g_scr[0][boff + t];
        sA[t] = a;
        sB[t] = g_scr[1][boff + t];
        sC[t] = g_scr[2][boff + t];
        cnt += (a >= 0.0f) ? 1.0f : 0.0f;
    }

    cnt = blockReduceSum1024(cnt);
    int k = (int)ceilf(cnt * 0.95f);
    if (k < 1) k = 1;
    if (k > TLEN) k = TLEN;

    float kth[3];
    radix_select3(sA, sB, sC, k, kth);
    float d1 = fixup_den(kth[0], sA);
    float d2 = fixup_den(kth[1], sB);
    float d3 = fixup_den(kth[2], sC);
    __syncthreads();

#pragma unroll
    for (int j = 0; j < 4; j++) {
        int t = j * 1024 + tid;
        float hc = sA[t];
        float s = 0.0f;
        if (hc >= 0.0f) {
            s = 0.35f * (hc / d1) + 0.30f * (sB[t] / d2) + 0.25f * (sC[t] / d3)
                + 0.10f * g_scr[3][boff + t];
        }
        sA[t] = s;
    }
    __syncthreads();

#pragma unroll
    for (int j = 0; j < 4; j++) {
        int t = j * 1024 + tid;
        float m0 = ms[t];
        float acc = 0.0f;
#pragma unroll
        for (int d = -2; d <= 2; d++) {
            int u = t + d;
            if (u >= 0 && u < TLEN) acc += sA[u];
        }
        float smv = acc * 0.2f * m0;
        sB[t] = (m0 > 0.5f) ? smv : -1.0f;
    }
    __syncthreads();

    float d4 = fixup_den(radix_select(sB, k), sB);
#pragma unroll
    for (int j = 0; j < 4; j++) {
        int t = j * 1024 + tid;
        float m0 = ms[t];
        float r = 0.0f;
        if (m0 > 0.5f) r = fminf(fmaxf(sB[t] / d4, 0.0f), 1.0f);
        g_rule[boff + t] = r;
    }
}

// ---------------- tf32 mma.sync implicit-GEMM conv (K=5, pad 2) — frozen R12 build ----
// CTA = (128-t chunk, batch row), 256 threads = 8 warps (4 t-groups x 2 n-halves);
// warp tile = 32t x 32o. A tile in smem; B fragments tf32 in GLOBAL (L1-resident).
// __launch_bounds__(256,4): regs<=64 -> 4 CTAs/SM = 32 warps.
// FUSE3: conv3 (1x1) + sigmoid folded in; halves combined via tiny smem buffer.
template <int CIN, bool FUSE3>
__global__ void __launch_bounds__(256, 4) conv_mma(const float* __restrict__ bias,
                                                   const float* __restrict__ w3,
                                                   const float* __restrict__ b3,
                                                   const float* __restrict__ amask) {
    constexpr int S = CIN / 8;
    constexpr int CINP = CIN + 4;
    constexpr int ROWS = 132;

    extern __shared__ float smem[];
    float* xs = smem;                 // [ROWS][CINP]
    __shared__ float sb2[64], sw3s[64];
    __shared__ float pr[256];         // FUSE3 half-sums [nh][128 t]

    const int b = blockIdx.y;
    const int t0 = blockIdx.x * 128;
    const int tid = threadIdx.x;
    const int wid = tid >> 5, lane = tid & 31;
    const int tg = wid >> 1, nh = wid & 1;
    const float* xg = (CIN == 16) ? g_featsA : g_h1;
    const float* wf = (CIN == 16) ? g_wf1 : g_wf2;

    if (tid < 64) {
        sb2[tid] = bias[tid];
        if (FUSE3) sw3s[tid] = w3[tid];
    }

    // X tile: rows t0-2 .. t0+129
    constexpr int Q = CIN / 4;
    for (int idx = tid; idx < ROWS * Q; idx += 256) {
        int r = idx / Q, q = idx - r * Q;
        int t = t0 - 2 + r;
        float4 v = make_float4(0.0f, 0.0f, 0.0f, 0.0f);
        if (t >= 0 && t < TLEN) v = ((const float4*)(xg + ((size_t)b * TLEN + t) * CIN))[q];
        ((float4*)(xs + r * CINP))[q] = v;
    }
    __syncthreads();

    float d[2][4][4];
#pragma unroll
    for (int mt = 0; mt < 2; mt++)
#pragma unroll
        for (int nt = 0; nt < 4; nt++)
#pragma unroll
            for (int j = 0; j < 4; j++) d[mt][nt][j] = 0.0f;

    const float* xbase = xs + (tg * 32 + (lane >> 2)) * CINP + (lane & 3);
    const float* wfl = wf + nh * 256 + lane * 2;  // [ks][ntg][lane][2]; ntg = nh*4 + ntl

    for (int tap = 0; tap < 5; tap++) {
        const float* xtap = xbase + tap * CINP;
#pragma unroll
        for (int s = 0; s < S; s++) {
            const float* xp = xtap + s * 8;
            uint32_t a[2][4];
#pragma unroll
            for (int mt = 0; mt < 2; mt++) {
                const float* xm = xp + mt * 16 * CINP;
                a[mt][0] = __float_as_uint(xm[0]);
                a[mt][1] = __float_as_uint(xm[8 * CINP]);
                a[mt][2] = __float_as_uint(xm[4]);
                a[mt][3] = __float_as_uint(xm[8 * CINP + 4]);
            }
            const float* wr = wfl + (tap * S + s) * 512;
#pragma unroll
            for (int nt = 0; nt < 4; nt++) {
                uint2 bv = __ldg((const uint2*)(wr + nt * 64));
                mma8(d[0][nt], a[0], bv);
                mma8(d[1][nt], a[1], bv);
            }
        }
    }

    if (!FUSE3) {
#pragma unroll
        for (int mt = 0; mt < 2; mt++)
#pragma unroll
            for (int rh = 0; rh < 2; rh++) {
                int t = t0 + tg * 32 + mt * 16 + rh * 8 + (lane >> 2);
                float* hb = g_h1 + ((size_t)b * TLEN + t) * 64;
#pragma unroll
                for (int nt = 0; nt < 4; nt++) {
                    int n = nh * 32 + nt * 8 + 2 * (lane & 3);
                    float2 v;
                    v.x = totf32(gelu_exact(d[mt][nt][2 * rh + 0] + sb2[n]));
                    v.y = totf32(gelu_exact(d[mt][nt][2 * rh + 1] + sb2[n + 1]));
                    *(float2*)(hb + n) = v;
                }
            }
    } else {
        float part[2][2] = {{0.0f, 0.0f}, {0.0f, 0.0f}};
#pragma unroll
        for (int nt = 0; nt < 4; nt++)
#pragma unroll
            for (int j = 0; j < 2; j++) {
                int o = nh * 32 + nt * 8 + 2 * (lane & 3) + j;
                float wv = sw3s[o], bv = sb2[o];
#pragma unroll
                for (int mt = 0; mt < 2; mt++) {
                    part[mt][0] += wv * gelu_exact(d[mt][nt][j] + bv);
                    part[mt][1] += wv * gelu_exact(d[mt][nt][2 + j] + bv);
                }
            }
#pragma unroll
        for (int mt = 0; mt < 2; mt++)
#pragma unroll
            for (int rh = 0; rh < 2; rh++) {
                float v = part[mt][rh];
                v += __shfl_xor_sync(0xffffffffu, v, 1);
                v += __shfl_xor_sync(0xffffffffu, v, 2);
                if ((lane & 3) == 0)
                    pr[nh * 128 + tg * 32 + mt * 16 + rh * 8 + (lane >> 2)] = v;
            }
        __syncthreads();
        if (tid < 128) {
            int t = t0 + tid;
            float v = pr[tid] + pr[128 + tid] + b3[0];
            float m = amask[(size_t)b * TLEN + t];
            g_lr[(size_t)b * TLEN + t] = sigmoidf(v) * m;
        }
    }
}

// ---------------- kernel: smooth learned, combine, clip ----------------
__global__ void __launch_bounds__(256) k_final(const float* __restrict__ amask,
                                               float* __restrict__ out) {
    int b = blockIdx.y;
    int t = blockIdx.x * 256 + threadIdx.x;
    const float* lr = g_lr + (size_t)b * TLEN;
    float m = amask[(size_t)b * TLEN + t];
    float acc = 0.0f;
#pragma unroll
    for (int d = -2; d <= 2; d++) {
        int u = t + d;
        if (u >= 0 && u < TLEN) acc += lr[u];
    }
    float learned = fminf(fmaxf(acc * 0.2f * m, 0.0f), 1.0f);
    float r = g_rule[(size_t)b * TLEN + t];
    float o = 0.5f * r + 0.5f * learned;
    out[(size_t)b * TLEN + t] = fminf(fmaxf(o, 0.0f), 1.0f) * m;
}

// ---------------- launch ----------------
extern "C" void kernel_launch(void* const* d_in, const int* in_sizes, int n_in,
                              void* d_out, int out_size) {
    const float* traj = (const float*)d_in[0];
    const float* intervals = (const float*)d_in[1];
    const float* amask = (const float*)d_in[2];
    const float* obs = (const float*)d_in[3];
    const float* w1 = (const float*)d_in[4];
    const float* b1 = (const float*)d_in[5];
    const float* w2 = (const float*)d_in[6];
    const float* b2 = (const float*)d_in[7];
    const float* w3 = (const float*)d_in[8];
    const float* b3 = (const float*)d_in[9];
    float* out = (float*)d_out;

    const int SMEM_RULE = 3 * TLEN * 4;              // 49152
    const int SMEM_C1 = 132 * 20 * 4;                // 10560
    const int SMEM_C2 = 132 * 68 * 4;                // 35904 (4 CTAs/SM: 143.6 KB)

    cudaFuncSetAttribute(k_rule, cudaFuncAttributeMaxDynamicSharedMemorySize, SMEM_RULE);

    // slot 4 = conv2 (what ncu -s 5 -c 1 catches)
    k_feat<<<dim3(TLEN / 256, BATCH), 256>>>(traj, intervals, amask, obs);
    k_prepw<<<50, 256>>>(w1, w2);
    conv_mma<16, false><<<dim3(TLEN / 128, BATCH), 256, SMEM_C1>>>(b1, w3, b3, amask);
    conv_mma<64, true><<<dim3(TLEN / 128, BATCH), 256, SMEM_C2>>>(b2, w3, b3, amask);
    k_rule<<<BATCH, 1024, SMEM_RULE>>>(amask);
    k_final<<<dim3(TLEN / 256, BATCH), 256>>>(amask, out);
}

// round 16
// speedup vs baseline: 1.0304x; 1.0304x over previous
#include <cuda_runtime.h>
#include <math.h>
#include <stdint.h>

typedef unsigned long long ull;

#define BATCH 128
#define TLEN 4096

// ---------------- scratch: static device globals (no allocations) ----------------
__device__ float g_featsA[(size_t)BATCH * TLEN * 16];  // [B][T][16] tf32-rounded, c>=10 zero
__device__ float g_h1[(size_t)BATCH * TLEN * 64];      // [B][T][64] tf32-rounded gelu(conv1)
__device__ float g_scr[4][(size_t)BATCH * TLEN];       // hcv/anv/scv (sentinel -1) + otv
__device__ float g_rule[(size_t)BATCH * TLEN];         // [B,T]
__device__ float g_lr[(size_t)BATCH * TLEN];           // [B,T] sigmoid(conv3)*mask
__device__ float g_wf2[40 * 512];                      // conv2 B fragments [ks][nt][lane][2]
__device__ float g_wf1[10 * 512];                      // conv1 B fragments

// ---------------- helpers ----------------
__device__ __forceinline__ float gelu_exact(float x) {
    return 0.5f * x * (1.0f + erff(x * 0.70710678118654752440f));
}
__device__ __forceinline__ float sigmoidf(float x) { return 1.0f / (1.0f + expf(-x)); }
__device__ __forceinline__ float safenorm2(float x, float y) {
    float s = x * x + y * y;
    return s > 0.0f ? sqrtf(s) : 0.0f;
}
__device__ __forceinline__ float totf32(float x) {
    float r;
    asm("cvt.rna.tf32.f32 %0,%1;" : "=f"(r) : "f"(x));
    return r;
}
// m16n8k8 tf32 MMA (HMMA path, valid on plain sm_103 target)
__device__ __forceinline__ void mma8(float* d, const uint32_t* a, uint2 b) {
    asm volatile(
        "mma.sync.aligned.m16n8k8.row.col.f32.tf32.tf32.f32 "
        "{%0,%1,%2,%3},{%4,%5,%6,%7},{%8,%9},{%0,%1,%2,%3};"
        : "+f"(d[0]), "+f"(d[1]), "+f"(d[2]), "+f"(d[3])
        : "r"(a[0]), "r"(a[1]), "r"(a[2]), "r"(a[3]), "r"(b.x), "r"(b.y));
}

// ---------------- block reductions (blockDim.x == 1024) ----------------
__device__ float blockReduceSum1024(float v) {
    __shared__ float red[32];
    __syncthreads();
#pragma unroll
    for (int o = 16; o > 0; o >>= 1) v += __shfl_xor_sync(0xffffffffu, v, o);
    if ((threadIdx.x & 31) == 0) red[threadIdx.x >> 5] = v;
    __syncthreads();
    if (threadIdx.x == 0) {
        float s = 0.0f;
        for (int i = 0; i < 32; i++) s += red[i];
        red[0] = s;
    }
    __syncthreads();
    float r = red[0];
    __syncthreads();
    return r;
}
__device__ float blockReduceMax1024(float v) {
    __shared__ float red[32];
    __syncthreads();
#pragma unroll
    for (int o = 16; o > 0; o >>= 1) v = fmaxf(v, __shfl_xor_sync(0xffffffffu, v, o));
    if ((threadIdx.x & 31) == 0) red[threadIdx.x >> 5] = v;
    __syncthreads();
    if (threadIdx.x == 0) {
        float s = red[0];
        for (int i = 1; i < 32; i++) s = fmaxf(s, red[i]);
        red[0] = s;
    }
    __syncthreads();
    float r = red[0];
    __syncthreads();
    return r;
}

// ---------------- exact k-th smallest: 3 concurrent MSD radix selects (1024 thr) -------
__device__ void radix_select3(const float* s0, const float* s1, const float* s2, int k,
                              float* kth) {
    __shared__ unsigned hist[3][256];
    __shared__ unsigned sh_pref[3];
    __shared__ int sh_k[3];
    unsigned pref[3] = {0u, 0u, 0u};
    int kk[3] = {k, k, k};
    int tid = threadIdx.x;
    for (int shift = 24; shift >= 0; shift -= 8) {
        __syncthreads();
        if (tid < 256) { hist[0][tid] = 0u; hist[1][tid] = 0u; hist[2][tid] = 0u; }
        __syncthreads();
        unsigned pmask = (shift == 24) ? 0u : (0xFFFFFFFFu << (shift + 8));
#pragma unroll
        for (int j = 0; j < 4; j++) {
            int t = j * 1024 + tid;
            float v0 = s0[t], v1 = s1[t], v2 = s2[t];
            unsigned k0 = (v0 >= 0.0f) ? __float_as_uint(v0) : 0xFFFFFFFFu;
            unsigned k1 = (v1 >= 0.0f) ? __float_as_uint(v1) : 0xFFFFFFFFu;
            unsigned k2 = (v2 >= 0.0f) ? __float_as_uint(v2) : 0xFFFFFFFFu;
            if ((k0 & pmask) == (pref[0] & pmask)) atomicAdd(&hist[0][(k0 >> shift) & 255u], 1u);
            if ((k1 & pmask) == (pref[1] & pmask)) atomicAdd(&hist[1][(k1 >> shift) & 255u], 1u);
            if ((k2 & pmask) == (pref[2] & pmask)) atomicAdd(&hist[2][(k2 >> shift) & 255u], 1u);
        }
        __syncthreads();
        if (tid < 96) {
            int w = tid >> 5, ln = tid & 31;
            unsigned loc[8], tot = 0u;
#pragma unroll
            for (int j = 0; j < 8; j++) { loc[j] = hist[w][ln * 8 + j]; tot += loc[j]; }
            unsigned inc = tot;
#pragma unroll
            for (int o = 1; o < 32; o <<= 1) {
                unsigned v = __shfl_up_sync(0xffffffffu, inc, o);
                if (ln >= o) inc += v;
            }
            unsigned cum = inc - tot;
            int kw = kk[w];
#pragma unroll
            for (int j = 0; j < 8; j++) {
                unsigned nc = cum + loc[j];
                if (cum < (unsigned)kw && (unsigned)kw <= nc) {
                    sh_pref[w] = pref[w] | ((unsigned)(ln * 8 + j) << shift);
                    sh_k[w] = kw - (int)cum;
                }
                cum = nc;
            }
        }
        __syncthreads();
#pragma unroll
        for (int w = 0; w < 3; w++) { pref[w] = sh_pref[w]; kk[w] = sh_k[w]; }
    }
    kth[0] = __uint_as_float(pref[0]);
    kth[1] = __uint_as_float(pref[1]);
    kth[2] = __uint_as_float(pref[2]);
}

__device__ float radix_select(const float* s, int k) {
    __shared__ unsigned hist[256];
    __shared__ unsigned sh_pref;
    __shared__ int sh_k;
    unsigned prefix = 0;
    int tid = threadIdx.x;
    for (int shift = 24; shift >= 0; shift -= 8) {
        __syncthreads();
        if (tid < 256) hist[tid] = 0u;
        __syncthreads();
        unsigned pmask = (shift == 24) ? 0u : (0xFFFFFFFFu << (shift + 8));
#pragma unroll
        for (int j = 0; j < 4; j++) {
            int t = j * 1024 + tid;
            float v = s[t];
            unsigned key = (v >= 0.0f) ? __float_as_uint(v) : 0xFFFFFFFFu;
            if ((key & pmask) == (prefix & pmask))
                atomicAdd(&hist[(key >> shift) & 0xFFu], 1u);
        }
        __syncthreads();
        if (tid < 32) {
            unsigned loc[8], tot = 0u;
#pragma unroll
            for (int j = 0; j < 8; j++) { loc[j] = hist[tid * 8 + j]; tot += loc[j]; }
            unsigned inc = tot;
#pragma unroll
            for (int o = 1; o < 32; o <<= 1) {
                unsigned v = __shfl_up_sync(0xffffffffu, inc, o);
                if (tid >= o) inc += v;
            }
            unsigned cum = inc - tot;
#pragma unroll
            for (int j = 0; j < 8; j++) {
                unsigned nc = cum + loc[j];
                if (cum < (unsigned)k && (unsigned)k <= nc) {
                    sh_pref = prefix | ((unsigned)(tid * 8 + j) << shift);
                    sh_k = k - (int)cum;
                }
                cum = nc;
            }
        }
        __syncthreads();
        prefix = sh_pref;
        k = sh_k;
    }
    return __uint_as_float(prefix);
}

__device__ float fixup_den(float kth, const float* s) {
    float mx = 0.0f;
    int tid = threadIdx.x;
#pragma unroll
    for (int j = 0; j < 4; j++) mx = fmaxf(mx, s[j * 1024 + tid]);
    mx = blockReduceMax1024(mx);
    float scale = fabsf(kth);
    if (scale < 1e-6f) scale = mx;
    return fmaxf(scale, 1e-6f);
}

// ---------------- kernel: per-timestep features (full-chip grid) ----------------
__global__ void __launch_bounds__(256) k_feat(const float* __restrict__ traj,
                                              const float* __restrict__ intervals,
                                              const float* __restrict__ amask,
                                              const float* __restrict__ obs) {
    int b = blockIdx.y;
    int t = blockIdx.x * 256 + threadIdx.x;
    const float* tr = traj + (size_t)b * TLEN * 2;
    const float* iv = intervals + (size_t)b * TLEN;
    const float* ms = amask + (size_t)b * TLEN;
    const float* ob = obs + (size_t)b * TLEN;

    float m0 = ms[t];
    float m1 = (t >= 1) ? ms[t - 1] : 0.0f;
    float m2 = (t >= 2) ? ms[t - 2] : 0.0f;
    bool v0 = m0 > 0.5f, v1 = m1 > 0.5f, v2 = m2 > 0.5f;
    float pm = (v0 && v1) ? 1.0f : 0.0f;
    float pm1 = (v1 && v2) ? 1.0f : 0.0f;
    float x0 = tr[2 * t] * m0, y0 = tr[2 * t + 1] * m0;
    float x1 = 0.0f, y1 = 0.0f, x2 = 0.0f, y2 = 0.0f, i1 = 0.0f, ob1 = 0.0f;
    if (t >= 1) { x1 = tr[2 * t - 2] * m1; y1 = tr[2 * t - 1] * m1; i1 = iv[t - 1]; ob1 = ob[t - 1]; }
    if (t >= 2) { x2 = tr[2 * t - 4] * m2; y2 = tr[2 * t - 3] * m2; }
    float i0 = iv[t], ob0 = ob[t];
    float dt0 = fmaxf(i0, 1e-3f), dt1 = fmaxf(i1, 1e-3f);
    float cdx = (t >= 1) ? (x0 - x1) * pm : 0.0f;
    float cdy = (t >= 1) ? (y0 - y1) * pm : 0.0f;
    float vx = cdx / dt0 * m0, vy = cdy / dt0 * m0;
    float cdx1 = (t >= 2) ? (x1 - x2) * pm1 : 0.0f;
    float cdy1 = (t >= 2) ? (y1 - y2) * pm1 : 0.0f;
    float vx1 = cdx1 / dt1 * m1, vy1 = cdy1 / dt1 * m1;
    float ax = (t >= 1) ? (vx - vx1) * pm / dt0 * m0 : 0.0f;
    float ay = (t >= 1) ? (vy - vy1) * pm / dt0 * m0 : 0.0f;
    float sp = safenorm2(vx, vy) * m0;
    float sp1 = safenorm2(vx1, vy1) * m1;
    float scv = (t >= 1) ? fabsf((sp - sp1) * pm) * m0 : 0.0f;
    float anv = safenorm2(ax, ay) * m0;

    // heading change: wrap(hd - hd1) == atan2(cross, dot) when BOTH velocity vectors
    // are nonzero; zero-vector cases take the exact reference path (atan2(0,0)=0).
    float wrapped;
    bool z0 = (vx == 0.0f && vy == 0.0f);
    bool z1 = (vx1 == 0.0f && vy1 == 0.0f);
    if (!z0 && !z1) {
        float cr = vy * vx1 - vx * vy1;
        float dp = vx * vx1 + vy * vy1;
        wrapped = atan2f(cr, dp);
    } else {
        float hd = atan2f(vy, vx), hd1 = atan2f(vy1, vx1);
        float dd = hd - hd1;
        wrapped = atan2f(sinf(dd), cosf(dd));
    }
    float hcv = (t >= 1) ? fabsf(wrapped) * pm * m0 : 0.0f;

    float otv = (t >= 1) ? fabsf(ob0 - ob1) * pm : 0.0f;
    otv = fminf(fmaxf(otv, 0.0f), 1.0f);

    // features [B][T][16] tf32-rounded, channels 10..15 zero
    float4* fb = (float4*)(g_featsA + ((size_t)b * TLEN + t) * 16);
    fb[0] = make_float4(totf32(x0), totf32(y0), totf32(vx), totf32(vy));
    fb[1] = make_float4(totf32(ax), totf32(ay), totf32(sp), totf32(hcv));
    fb[2] = make_float4(totf32(i0 * m0), totf32(ob0 * m0), 0.0f, 0.0f);
    fb[3] = make_float4(0.0f, 0.0f, 0.0f, 0.0f);

    size_t off = (size_t)b * TLEN + t;
    g_scr[0][off] = v0 ? hcv : -1.0f;
    g_scr[1][off] = v0 ? anv : -1.0f;
    g_scr[2][off] = v0 ? scv : -1.0f;
    g_scr[3][off] = otv;
}

// ---------------- kernel: build tf32 B-fragment tables in global ----------------
// block 0..39: conv2 k-step; block 40..49: conv1 k-step. 256 threads = [nt(8)][lane(32)].
__global__ void __launch_bounds__(256) k_prepw(const float* __restrict__ w1,
                                               const float* __restrict__ w2) {
    int idx = threadIdx.x;
    int ln = idx & 31;
    int nt = idx >> 5;
    int n = nt * 8 + (ln >> 2);
    if (blockIdx.x < 40) {
        int ks = blockIdx.x;
        int tap = ks >> 3, s = ks & 7;
        int c0 = s * 8 + (ln & 3);
        float v0 = w2[(n * 64 + c0) * 5 + tap];
        float v1 = w2[(n * 64 + c0 + 4) * 5 + tap];
        *(float2*)(g_wf2 + ks * 512 + idx * 2) = make_float2(totf32(v0), totf32(v1));
    } else {
        int ks = blockIdx.x - 40;
        int tap = ks >> 1, s = ks & 1;
        int c0 = s * 8 + (ln & 3);
        float v0 = (c0 < 10) ? w1[(n * 10 + c0) * 5 + tap] : 0.0f;
        float v1 = (c0 + 4 < 10) ? w1[(n * 10 + c0 + 4) * 5 + tap] : 0.0f;
        *(float2*)(g_wf1 + ks * 512 + idx * 2) = make_float2(totf32(v0), totf32(v1));
    }
}

// ---------------- kernel: rule scores (1 CTA per batch row, 1024 threads) ----------
__global__ void __launch_bounds__(1024) k_rule(const float* __restrict__ amask) {
    extern __shared__ float smx[];
    float* sA = smx;
    float* sB = smx + TLEN;
    float* sC = smx + 2 * TLEN;

    int b = blockIdx.x;
    int tid = threadIdx.x;
    const float* ms = amask + (size_t)b * TLEN;
    size_t boff = (size_t)b * TLEN;

    float cnt = 0.0f;
#pragma unroll
    for (int j = 0; j < 4; j++) {
        int t = j * 1024 + tid;
        float a = g_scr[0][boff + t];
        sA[t] = a;
        sB[t] = g_scr[1][boff + t];
        sC[t] = g_scr[2][boff + t];
        cnt += (a >= 0.0f) ? 1.0f : 0.0f;
    }

    cnt = blockReduceSum1024(cnt);
    int k = (int)ceilf(cnt * 0.95f);
    if (k < 1) k = 1;
    if (k > TLEN) k = TLEN;

    float kth[3];
    radix_select3(sA, sB, sC, k, kth);
    float d1 = fixup_den(kth[0], sA);
    float d2 = fixup_den(kth[1], sB);
    float d3 = fixup_den(kth[2], sC);
    __syncthreads();

#pragma unroll
    for (int j = 0; j < 4; j++) {
        int t = j * 1024 + tid;
        float hc = sA[t];
        float s = 0.0f;
        if (hc >= 0.0f) {
            s = 0.35f * (hc / d1) + 0.30f * (sB[t] / d2) + 0.25f * (sC[t] / d3)
                + 0.10f * g_scr[3][boff + t];
        }
        sA[t] = s;
    }
    __syncthreads();

#pragma unroll
    for (int j = 0; j < 4; j++) {
        int t = j * 1024 + tid;
        float m0 = ms[t];
        float acc = 0.0f;
#pragma unroll
        for (int d = -2; d <= 2; d++) {
            int u = t + d;
            if (u >= 0 && u < TLEN) acc += sA[u];
        }
        float smv = acc * 0.2f * m0;
        sB[t] = (m0 > 0.5f) ? smv : -1.0f;
    }
    __syncthreads();

    float d4 = fixup_den(radix_select(sB, k), sB);
#pragma unroll
    for (int j = 0; j < 4; j++) {
        int t = j * 1024 + tid;
        float m0 = ms[t];
        float r = 0.0f;
        if (m0 > 0.5f) r = fminf(fmaxf(sB[t] / d4, 0.0f), 1.0f);
        g_rule[boff + t] = r;
    }
}

// ---------------- tf32 mma.sync implicit-GEMM conv (K=5, pad 2) — frozen R12 build ----
// CTA = (128-t chunk, batch row), 256 threads = 8 warps (4 t-groups x 2 n-halves);
// warp tile = 32t x 32o. A tile in smem; B fragments tf32 in GLOBAL (L1-resident).
// __launch_bounds__(256,4): regs<=64 -> 4 CTAs/SM = 32 warps.
// FUSE3: conv3 (1x1) + sigmoid folded in; halves combined via tiny smem buffer.
template <int CIN, bool FUSE3>
__global__ void __launch_bounds__(256, 4) conv_mma(const float* __restrict__ bias,
                                                   const float* __restrict__ w3,
                                                   const float* __restrict__ b3,
                                                   const float* __restrict__ amask) {
    constexpr int S = CIN / 8;
    constexpr int CINP = CIN + 4;
    constexpr int ROWS = 132;

    extern __shared__ float smem[];
    float* xs = smem;                 // [ROWS][CINP]
    __shared__ float sb2[64], sw3s[64];
    __shared__ float pr[256];         // FUSE3 half-sums [nh][128 t]

    const int b = blockIdx.y;
    const int t0 = blockIdx.x * 128;
    const int tid = threadIdx.x;
    const int wid = tid >> 5, lane = tid & 31;
    const int tg = wid >> 1, nh = wid & 1;
    const float* xg = (CIN == 16) ? g_featsA : g_h1;
    const float* wf = (CIN == 16) ? g_wf1 : g_wf2;

    if (tid < 64) {
        sb2[tid] = bias[tid];
        if (FUSE3) sw3s[tid] = w3[tid];
    }

    // X tile: rows t0-2 .. t0+129
    constexpr int Q = CIN / 4;
    for (int idx = tid; idx < ROWS * Q; idx += 256) {
        int r = idx / Q, q = idx - r * Q;
        int t = t0 - 2 + r;
        float4 v = make_float4(0.0f, 0.0f, 0.0f, 0.0f);
        if (t >= 0 && t < TLEN) v = ((const float4*)(xg + ((size_t)b * TLEN + t) * CIN))[q];
        ((float4*)(xs + r * CINP))[q] = v;
    }
    __syncthreads();

    float d[2][4][4];
#pragma unroll
    for (int mt = 0; mt < 2; mt++)
#pragma unroll
        for (int nt = 0; nt < 4; nt++)
#pragma unroll
            for (int j = 0; j < 4; j++) d[mt][nt][j] = 0.0f;

    const float* xbase = xs + (tg * 32 + (lane >> 2)) * CINP + (lane & 3);
    const float* wfl = wf + nh * 256 + lane * 2;  // [ks][ntg][lane][2]; ntg = nh*4 + ntl

    for (int tap = 0; tap < 5; tap++) {
        const float* xtap = xbase + tap * CINP;
#pragma unroll
        for (int s = 0; s < S; s++) {
            const float* xp = xtap + s * 8;
            uint32_t a[2][4];
#pragma unroll
            for (int mt = 0; mt < 2; mt++) {
                const float* xm = xp + mt * 16 * CINP;
                a[mt][0] = __float_as_uint(xm[0]);
                a[mt][1] = __float_as_uint(xm[8 * CINP]);
                a[mt][2] = __float_as_uint(xm[4]);
                a[mt][3] = __float_as_uint(xm[8 * CINP + 4]);
            }
            const float* wr = wfl + (tap * S + s) * 512;
#pragma unroll
            for (int nt = 0; nt < 4; nt++) {
                uint2 bv = __ldg((const uint2*)(wr + nt * 64));
                mma8(d[0][nt], a[0], bv);
                mma8(d[1][nt], a[1], bv);
            }
        }
    }

    if (!FUSE3) {
#pragma unroll
        for (int mt = 0; mt < 2; mt++)
#pragma unroll
            for (int rh = 0; rh < 2; rh++) {
                int t = t0 + tg * 32 + mt * 16 + rh * 8 + (lane >> 2);
                float* hb = g_h1 + ((size_t)b * TLEN + t) * 64;
#pragma unroll
                for (int nt = 0; nt < 4; nt++) {
                    int n = nh * 32 + nt * 8 + 2 * (lane & 3);
                    float2 v;
                    v.x = totf32(gelu_exact(d[mt][nt][2 * rh + 0] + sb2[n]));
                    v.y = totf32(gelu_exact(d[mt][nt][2 * rh + 1] + sb2[n + 1]));
                    *(float2*)(hb + n) = v;
                }
            }
    } else {
        float part[2][2] = {{0.0f, 0.0f}, {0.0f, 0.0f}};
#pragma unroll
        for (int nt = 0; nt < 4; nt++)
#pragma unroll
            for (int j = 0; j < 2; j++) {
                int o = nh * 32 + nt * 8 + 2 * (lane & 3) + j;
                float wv = sw3s[o], bv = sb2[o];
#pragma unroll
                for (int mt = 0; mt < 2; mt++) {
                    part[mt][0] += wv * gelu_exact(d[mt][nt][j] + bv);
                    part[mt][1] += wv * gelu_exact(d[mt][nt][2 + j] + bv);
                }
            }
#pragma unroll
        for (int mt = 0; mt < 2; mt++)
#pragma unroll
            for (int rh = 0; rh < 2; rh++) {
                float v = part[mt][rh];
                v += __shfl_xor_sync(0xffffffffu, v, 1);
                v += __shfl_xor_sync(0xffffffffu, v, 2);
                if ((lane & 3) == 0)
                    pr[nh * 128 + tg * 32 + mt * 16 + rh * 8 + (lane >> 2)] = v;
            }
        __syncthreads();
        if (tid < 128) {
            int t = t0 + tid;
            float v = pr[tid] + pr[128 + tid] + b3[0];
            float m = amask[(size_t)b * TLEN + t];
            g_lr[(size_t)b * TLEN + t] = sigmoidf(v) * m;
        }
    }
}

// ---------------- kernel: smooth learned, combine, clip ----------------
__global__ void __launch_bounds__(256) k_final(const float* __restrict__ amask,
                                               float* __restrict__ out) {
    int b = blockIdx.y;
    int t = blockIdx.x * 256 + threadIdx.x;
    const float* lr = g_lr + (size_t)b * TLEN;
    float m = amask[(size_t)b * TLEN + t];
    float acc = 0.0f;
#pragma unroll
    for (int d = -2; d <= 2; d++) {
        int u = t + d;
        if (u >= 0 && u < TLEN) acc += lr[u];
    }
    float learned = fminf(fmaxf(acc * 0.2f * m, 0.0f), 1.0f);
    float r = g_rule[(size_t)b * TLEN + t];
    float o = 0.5f * r + 0.5f * learned;
    out[(size_t)b * TLEN + t] = fminf(fmaxf(o, 0.0f), 1.0f) * m;
}

// ---------------- launch: DAG with side-stream overlap (graph-capture safe) ----------
extern "C" void kernel_launch(void* const* d_in, const int* in_sizes, int n_in,
                              void* d_out, int out_size) {
    const float* traj = (const float*)d_in[0];
    const float* intervals = (const float*)d_in[1];
    const float* amask = (const float*)d_in[2];
    const float* obs = (const float*)d_in[3];
    const float* w1 = (const float*)d_in[4];
    const float* b1 = (const float*)d_in[5];
    const float* w2 = (const float*)d_in[6];
    const float* b2 = (const float*)d_in[7];
    const float* w3 = (const float*)d_in[8];
    const float* b3 = (const float*)d_in[9];
    float* out = (float*)d_out;

    const int SMEM_RULE = 3 * TLEN * 4;              // 49152
    const int SMEM_C1 = 132 * 20 * 4;                // 10560
    const int SMEM_C2 = 132 * 68 * 4;                // 35904 (4 CTAs/SM: 143.6 KB)

    cudaFuncSetAttribute(k_rule, cudaFuncAttributeMaxDynamicSharedMemorySize, SMEM_RULE);

    // one-time host-side handles (no device memory; identical work every call)
    static cudaStream_t s2 = nullptr;
    static cudaEvent_t evStart = nullptr, evFeat = nullptr, evPrep = nullptr,
                       evRule = nullptr;
    if (s2 == nullptr) {
        cudaStreamCreateWithFlags(&s2, cudaStreamNonBlocking);
        cudaEventCreateWithFlags(&evStart, cudaEventDisableTiming);
        cudaEventCreateWithFlags(&evFeat, cudaEventDisableTiming);
        cudaEventCreateWithFlags(&evPrep, cudaEventDisableTiming);
        cudaEventCreateWithFlags(&evRule, cudaEventDisableTiming);
    }
    cudaStream_t s0 = 0;  // origin (capture) stream

    // fork side stream
    cudaEventRecord(evStart, s0);
    cudaStreamWaitEvent(s2, evStart, 0);

    // s2: weight-fragment prep (independent of k_feat)
    k_prepw<<<50, 256, 0, s2>>>(w1, w2);
    cudaEventRecord(evPrep, s2);

    // s0: features
    k_feat<<<dim3(TLEN / 256, BATCH), 256, 0, s0>>>(traj, intervals, amask, obs);
    cudaEventRecord(evFeat, s0);

    // s2: rule scores depend only on k_feat -> overlap with conv1+conv2
    cudaStreamWaitEvent(s2, evFeat, 0);
    k_rule<<<BATCH, 1024, SMEM_RULE, s2>>>(amask);
    cudaEventRecord(evRule, s2);

    // s0: convs (conv1 needs featsA + wf1)
    cudaStreamWaitEvent(s0, evPrep, 0);
    conv_mma<16, false><<<dim3(TLEN / 128, BATCH), 256, SMEM_C1, s0>>>(b1, w3, b3, amask);
    conv_mma<64, true><<<dim3(TLEN / 128, BATCH), 256, SMEM_C2, s0>>>(b2, w3, b3, amask);

    // join and finalize
    cudaStreamWaitEvent(s0, evRule, 0);
    k_final<<<dim3(TLEN / 256, BATCH), 256, 0, s0>>>(amask, out);
}

// round 17
// speedup vs baseline: 1.0688x; 1.0373x over previous
#include <cuda_runtime.h>
#include <cuda_fp16.h>
#include <math.h>
#include <stdint.h>

typedef unsigned long long ull;

#define BATCH 128
#define TLEN 4096

// ---------------- scratch: static device globals (no allocations) ----------------
__device__ float g_featsA[(size_t)BATCH * TLEN * 16];  // [B][T][16] tf32-rounded, c>=10 zero
__device__ __half g_h1[(size_t)BATCH * TLEN * 64];     // [B][T][64] fp16 (== tf32 mantissa)
__device__ float g_scr[4][(size_t)BATCH * TLEN];       // hcv/anv/scv (sentinel -1) + otv
__device__ float g_rule[(size_t)BATCH * TLEN];         // [B,T]
__device__ float g_lr[(size_t)BATCH * TLEN];           // [B,T] sigmoid(conv3)*mask
__device__ float g_wf2[40 * 512];                      // conv2 B fragments [ks][nt][lane][2]
__device__ float g_wf1[10 * 512];                      // conv1 B fragments

// ---------------- helpers ----------------
__device__ __forceinline__ float gelu_exact(float x) {
    return 0.5f * x * (1.0f + erff(x * 0.70710678118654752440f));
}
__device__ __forceinline__ float sigmoidf(float x) { return 1.0f / (1.0f + expf(-x)); }
__device__ __forceinline__ float safenorm2(float x, float y) {
    float s = x * x + y * y;
    return s > 0.0f ? sqrtf(s) : 0.0f;
}
__device__ __forceinline__ float totf32(float x) {
    float r;
    asm("cvt.rna.tf32.f32 %0,%1;" : "=f"(r) : "f"(x));
    return r;
}
// m16n8k8 tf32 MMA (HMMA path, valid on plain sm_103 target)
__device__ __forceinline__ void mma8(float* d, const uint32_t* a, uint2 b) {
    asm volatile(
        "mma.sync.aligned.m16n8k8.row.col.f32.tf32.tf32.f32 "
        "{%0,%1,%2,%3},{%4,%5,%6,%7},{%8,%9},{%0,%1,%2,%3};"
        : "+f"(d[0]), "+f"(d[1]), "+f"(d[2]), "+f"(d[3])
        : "r"(a[0]), "r"(a[1]), "r"(a[2]), "r"(a[3]), "r"(b.x), "r"(b.y));
}

// ---------------- block reductions (blockDim.x == 1024) ----------------
__device__ float blockReduceSum1024(float v) {
    __shared__ float red[32];
    __syncthreads();
#pragma unroll
    for (int o = 16; o > 0; o >>= 1) v += __shfl_xor_sync(0xffffffffu, v, o);
    if ((threadIdx.x & 31) == 0) red[threadIdx.x >> 5] = v;
    __syncthreads();
    if (threadIdx.x == 0) {
        float s = 0.0f;
        for (int i = 0; i < 32; i++) s += red[i];
        red[0] = s;
    }
    __syncthreads();
    float r = red[0];
    __syncthreads();
    return r;
}
__device__ float blockReduceMax1024(float v) {
    __shared__ float red[32];
    __syncthreads();
#pragma unroll
    for (int o = 16; o > 0; o >>= 1) v = fmaxf(v, __shfl_xor_sync(0xffffffffu, v, o));
    if ((threadIdx.x & 31) == 0) red[threadIdx.x >> 5] = v;
    __syncthreads();
    if (threadIdx.x == 0) {
        float s = red[0];
        for (int i = 1; i < 32; i++) s = fmaxf(s, red[i]);
        red[0] = s;
    }
    __syncthreads();
    float r = red[0];
    __syncthreads();
    return r;
}

// ---------------- exact k-th smallest: 3 concurrent MSD radix selects (1024 thr) -------
__device__ void radix_select3(const float* s0, const float* s1, const float* s2, int k,
                              float* kth) {
    __shared__ unsigned hist[3][256];
    __shared__ unsigned sh_pref[3];
    __shared__ int sh_k[3];
    unsigned pref[3] = {0u, 0u, 0u};
    int kk[3] = {k, k, k};
    int tid = threadIdx.x;
    for (int shift = 24; shift >= 0; shift -= 8) {
        __syncthreads();
        if (tid < 256) { hist[0][tid] = 0u; hist[1][tid] = 0u; hist[2][tid] = 0u; }
        __syncthreads();
        unsigned pmask = (shift == 24) ? 0u : (0xFFFFFFFFu << (shift + 8));
#pragma unroll
        for (int j = 0; j < 4; j++) {
            int t = j * 1024 + tid;
            float v0 = s0[t], v1 = s1[t], v2 = s2[t];
            unsigned k0 = (v0 >= 0.0f) ? __float_as_uint(v0) : 0xFFFFFFFFu;
            unsigned k1 = (v1 >= 0.0f) ? __float_as_uint(v1) : 0xFFFFFFFFu;
            unsigned k2 = (v2 >= 0.0f) ? __float_as_uint(v2) : 0xFFFFFFFFu;
            if ((k0 & pmask) == (pref[0] & pmask)) atomicAdd(&hist[0][(k0 >> shift) & 255u], 1u);
            if ((k1 & pmask) == (pref[1] & pmask)) atomicAdd(&hist[1][(k1 >> shift) & 255u], 1u);
            if ((k2 & pmask) == (pref[2] & pmask)) atomicAdd(&hist[2][(k2 >> shift) & 255u], 1u);
        }
        __syncthreads();
        if (tid < 96) {
            int w = tid >> 5, ln = tid & 31;
            unsigned loc[8], tot = 0u;
#pragma unroll
            for (int j = 0; j < 8; j++) { loc[j] = hist[w][ln * 8 + j]; tot += loc[j]; }
            unsigned inc = tot;
#pragma unroll
            for (int o = 1; o < 32; o <<= 1) {
                unsigned v = __shfl_up_sync(0xffffffffu, inc, o);
                if (ln >= o) inc += v;
            }
            unsigned cum = inc - tot;
            int kw = kk[w];
#pragma unroll
            for (int j = 0; j < 8; j++) {
                unsigned nc = cum + loc[j];
                if (cum < (unsigned)kw && (unsigned)kw <= nc) {
                    sh_pref[w] = pref[w] | ((unsigned)(ln * 8 + j) << shift);
                    sh_k[w] = kw - (int)cum;
                }
                cum = nc;
            }
        }
        __syncthreads();
#pragma unroll
        for (int w = 0; w < 3; w++) { pref[w] = sh_pref[w]; kk[w] = sh_k[w]; }
    }
    kth[0] = __uint_as_float(pref[0]);
    kth[1] = __uint_as_float(pref[1]);
    kth[2] = __uint_as_float(pref[2]);
}

__device__ float radix_select(const float* s, int k) {
    __shared__ unsigned hist[256];
    __shared__ unsigned sh_pref;
    __shared__ int sh_k;
    unsigned prefix = 0;
    int tid = threadIdx.x;
    for (int shift = 24; shift >= 0; shift -= 8) {
        __syncthreads();
        if (tid < 256) hist[tid] = 0u;
        __syncthreads();
        unsigned pmask = (shift == 24) ? 0u : (0xFFFFFFFFu << (shift + 8));
#pragma unroll
        for (int j = 0; j < 4; j++) {
            int t = j * 1024 + tid;
            float v = s[t];
            unsigned key = (v >= 0.0f) ? __float_as_uint(v) : 0xFFFFFFFFu;
            if ((key & pmask) == (prefix & pmask))
                atomicAdd(&hist[(key >> shift) & 0xFFu], 1u);
        }
        __syncthreads();
        if (tid < 32) {
            unsigned loc[8], tot = 0u;
#pragma unroll
            for (int j = 0; j < 8; j++) { loc[j] = hist[tid * 8 + j]; tot += loc[j]; }
            unsigned inc = tot;
#pragma unroll
            for (int o = 1; o < 32; o <<= 1) {
                unsigned v = __shfl_up_sync(0xffffffffu, inc, o);
                if (tid >= o) inc += v;
            }
            unsigned cum = inc - tot;
#pragma unroll
            for (int j = 0; j < 8; j++) {
                unsigned nc = cum + loc[j];
                if (cum < (unsigned)k && (unsigned)k <= nc) {
                    sh_pref = prefix | ((unsigned)(tid * 8 + j) << shift);
                    sh_k = k - (int)cum;
                }
                cum = nc;
            }
        }
        __syncthreads();
        prefix = sh_pref;
        k = sh_k;
    }
    return __uint_as_float(prefix);
}

__device__ float fixup_den(float kth, const float* s) {
    float mx = 0.0f;
    int tid = threadIdx.x;
#pragma unroll
    for (int j = 0; j < 4; j++) mx = fmaxf(mx, s[j * 1024 + tid]);
    mx = blockReduceMax1024(mx);
    float scale = fabsf(kth);
    if (scale < 1e-6f) scale = mx;
    return fmaxf(scale, 1e-6f);
}

// ---------------- kernel: per-timestep features (full-chip grid) ----------------
__global__ void __launch_bounds__(256) k_feat(const float* __restrict__ traj,
                                              const float* __restrict__ intervals,
                                              const float* __restrict__ amask,
                                              const float* __restrict__ obs) {
    int b = blockIdx.y;
    int t = blockIdx.x * 256 + threadIdx.x;
    const float* tr = traj + (size_t)b * TLEN * 2;
    const float* iv = intervals + (size_t)b * TLEN;
    const float* ms = amask + (size_t)b * TLEN;
    const float* ob = obs + (size_t)b * TLEN;

    float m0 = ms[t];
    float m1 = (t >= 1) ? ms[t - 1] : 0.0f;
    float m2 = (t >= 2) ? ms[t - 2] : 0.0f;
    bool v0 = m0 > 0.5f, v1 = m1 > 0.5f, v2 = m2 > 0.5f;
    float pm = (v0 && v1) ? 1.0f : 0.0f;
    float pm1 = (v1 && v2) ? 1.0f : 0.0f;
    float x0 = tr[2 * t] * m0, y0 = tr[2 * t + 1] * m0;
    float x1 = 0.0f, y1 = 0.0f, x2 = 0.0f, y2 = 0.0f, i1 = 0.0f, ob1 = 0.0f;
    if (t >= 1) { x1 = tr[2 * t - 2] * m1; y1 = tr[2 * t - 1] * m1; i1 = iv[t - 1]; ob1 = ob[t - 1]; }
    if (t >= 2) { x2 = tr[2 * t - 4] * m2; y2 = tr[2 * t - 3] * m2; }
    float i0 = iv[t], ob0 = ob[t];
    float dt0 = fmaxf(i0, 1e-3f), dt1 = fmaxf(i1, 1e-3f);
    float cdx = (t >= 1) ? (x0 - x1) * pm : 0.0f;
    float cdy = (t >= 1) ? (y0 - y1) * pm : 0.0f;
    float vx = cdx / dt0 * m0, vy = cdy / dt0 * m0;
    float cdx1 = (t >= 2) ? (x1 - x2) * pm1 : 0.0f;
    float cdy1 = (t >= 2) ? (y1 - y2) * pm1 : 0.0f;
    float vx1 = cdx1 / dt1 * m1, vy1 = cdy1 / dt1 * m1;
    float ax = (t >= 1) ? (vx - vx1) * pm / dt0 * m0 : 0.0f;
    float ay = (t >= 1) ? (vy - vy1) * pm / dt0 * m0 : 0.0f;
    float sp = safenorm2(vx, vy) * m0;
    float sp1 = safenorm2(vx1, vy1) * m1;
    float scv = (t >= 1) ? fabsf((sp - sp1) * pm) * m0 : 0.0f;
    float anv = safenorm2(ax, ay) * m0;

    // heading change: wrap(hd - hd1) == atan2(cross, dot) when BOTH velocity vectors
    // are nonzero; zero-vector cases take the exact reference path (atan2(0,0)=0).
    float wrapped;
    bool z0 = (vx == 0.0f && vy == 0.0f);
    bool z1 = (vx1 == 0.0f && vy1 == 0.0f);
    if (!z0 && !z1) {
        float cr = vy * vx1 - vx * vy1;
        float dp = vx * vx1 + vy * vy1;
        wrapped = atan2f(cr, dp);
    } else {
        float hd = atan2f(vy, vx), hd1 = atan2f(vy1, vx1);
        float dd = hd - hd1;
        wrapped = atan2f(sinf(dd), cosf(dd));
    }
    float hcv = (t >= 1) ? fabsf(wrapped) * pm * m0 : 0.0f;

    float otv = (t >= 1) ? fabsf(ob0 - ob1) * pm : 0.0f;
    otv = fminf(fmaxf(otv, 0.0f), 1.0f);

    // features [B][T][16] tf32-rounded, channels 10..15 zero
    float4* fb = (float4*)(g_featsA + ((size_t)b * TLEN + t) * 16);
    fb[0] = make_float4(totf32(x0), totf32(y0), totf32(vx), totf32(vy));
    fb[1] = make_float4(totf32(ax), totf32(ay), totf32(sp), totf32(hcv));
    fb[2] = make_float4(totf32(i0 * m0), totf32(ob0 * m0), 0.0f, 0.0f);
    fb[3] = make_float4(0.0f, 0.0f, 0.0f, 0.0f);

    size_t off = (size_t)b * TLEN + t;
    g_scr[0][off] = v0 ? hcv : -1.0f;
    g_scr[1][off] = v0 ? anv : -1.0f;
    g_scr[2][off] = v0 ? scv : -1.0f;
    g_scr[3][off] = otv;
}

// ---------------- kernel: build tf32 B-fragment tables in global ----------------
// block 0..39: conv2 k-step; block 40..49: conv1 k-step. 256 threads = [nt(8)][lane(32)].
__global__ void __launch_bounds__(256) k_prepw(const float* __restrict__ w1,
                                               const float* __restrict__ w2) {
    int idx = threadIdx.x;
    int ln = idx & 31;
    int nt = idx >> 5;
    int n = nt * 8 + (ln >> 2);
    if (blockIdx.x < 40) {
        int ks = blockIdx.x;
        int tap = ks >> 3, s = ks & 7;
        int c0 = s * 8 + (ln & 3);
        float v0 = w2[(n * 64 + c0) * 5 + tap];
        float v1 = w2[(n * 64 + c0 + 4) * 5 + tap];
        *(float2*)(g_wf2 + ks * 512 + idx * 2) = make_float2(totf32(v0), totf32(v1));
    } else {
        int ks = blockIdx.x - 40;
        int tap = ks >> 1, s = ks & 1;
        int c0 = s * 8 + (ln & 3);
        float v0 = (c0 < 10) ? w1[(n * 10 + c0) * 5 + tap] : 0.0f;
        float v1 = (c0 + 4 < 10) ? w1[(n * 10 + c0 + 4) * 5 + tap] : 0.0f;
        *(float2*)(g_wf1 + ks * 512 + idx * 2) = make_float2(totf32(v0), totf32(v1));
    }
}

// ---------------- kernel: rule scores (1 CTA per batch row, 1024 threads) ----------
__global__ void __launch_bounds__(1024) k_rule(const float* __restrict__ amask) {
    extern __shared__ float smx[];
    float* sA = smx;
    float* sB = smx + TLEN;
    float* sC = smx + 2 * TLEN;

    int b = blockIdx.x;
    int tid = threadIdx.x;
    const float* ms = amask + (size_t)b * TLEN;
    size_t boff = (size_t)b * TLEN;

    float cnt = 0.0f;
#pragma unroll
    for (int j = 0; j < 4; j++) {
        int t = j * 1024 + tid;
        float a = g_scr[0][boff + t];
        sA[t] = a;
        sB[t] = g_scr[1][boff + t];
        sC[t] = g_scr[2][boff + t];
        cnt += (a >= 0.0f) ? 1.0f : 0.0f;
    }

    cnt = blockReduceSum1024(cnt);
    int k = (int)ceilf(cnt * 0.95f);
    if (k < 1) k = 1;
    if (k > TLEN) k = TLEN;

    float kth[3];
    radix_select3(sA, sB, sC, k, kth);
    float d1 = fixup_den(kth[0], sA);
    float d2 = fixup_den(kth[1], sB);
    float d3 = fixup_den(kth[2], sC);
    __syncthreads();

#pragma unroll
    for (int j = 0; j < 4; j++) {
        int t = j * 1024 + tid;
        float hc = sA[t];
        float s = 0.0f;
        if (hc >= 0.0f) {
            s = 0.35f * (hc / d1) + 0.30f * (sB[t] / d2) + 0.25f * (sC[t] / d3)
                + 0.10f * g_scr[3][boff + t];
        }
        sA[t] = s;
    }
    __syncthreads();

#pragma unroll
    for (int j = 0; j < 4; j++) {
        int t = j * 1024 + tid;
        float m0 = ms[t];
        float acc = 0.0f;
#pragma unroll
        for (int d = -2; d <= 2; d++) {
            int u = t + d;
            if (u >= 0 && u < TLEN) acc += sA[u];
        }
        float smv = acc * 0.2f * m0;
        sB[t] = (m0 > 0.5f) ? smv : -1.0f;
    }
    __syncthreads();

    float d4 = fixup_den(radix_select(sB, k), sB);
#pragma unroll
    for (int j = 0; j < 4; j++) {
        int t = j * 1024 + tid;
        float m0 = ms[t];
        float r = 0.0f;
        if (m0 > 0.5f) r = fminf(fmaxf(sB[t] / d4, 0.0f), 1.0f);
        g_rule[boff + t] = r;
    }
}

// ---------------- tf32 mma.sync implicit-GEMM conv (K=5, pad 2) ----------------
// Frozen R12 mainloop. h1 stored fp16 (mantissa == tf32 -> exact round-trip in
// normal range): conv1 epilogue stores half2, conv2 prologue converts half->float
// while filling the fp32 smem A-tile. 4 CTAs/SM (regs<=64).
template <int CIN, bool FUSE3>
__global__ void __launch_bounds__(256, 4) conv_mma(const float* __restrict__ bias,
                                                   const float* __restrict__ w3,
                                                   const float* __restrict__ b3,
                                                   const float* __restrict__ amask) {
    constexpr int S = CIN / 8;
    constexpr int CINP = CIN + 4;
    constexpr int ROWS = 132;

    extern __shared__ float smem[];
    float* xs = smem;                 // [ROWS][CINP]
    __shared__ float sb2[64], sw3s[64];
    __shared__ float pr[256];         // FUSE3 half-sums [nh][128 t]

    const int b = blockIdx.y;
    const int t0 = blockIdx.x * 128;
    const int tid = threadIdx.x;
    const int wid = tid >> 5, lane = tid & 31;
    const int tg = wid >> 1, nh = wid & 1;
    const float* wf = (CIN == 16) ? g_wf1 : g_wf2;

    if (tid < 64) {
        sb2[tid] = bias[tid];
        if (FUSE3) sw3s[tid] = w3[tid];
    }

    // X tile: rows t0-2 .. t0+129
    constexpr int Q = CIN / 4;
    for (int idx = tid; idx < ROWS * Q; idx += 256) {
        int r = idx / Q, q = idx - r * Q;
        int t = t0 - 2 + r;
        float4 v = make_float4(0.0f, 0.0f, 0.0f, 0.0f);
        if (t >= 0 && t < TLEN) {
            if (CIN == 16) {
                v = ((const float4*)(g_featsA + ((size_t)b * TLEN + t) * 16))[q];
            } else {
                uint2 raw = ((const uint2*)(g_h1 + ((size_t)b * TLEN + t) * 64))[q];
                __half2 ha = *(__half2*)&raw.x;
                __half2 hb = *(__half2*)&raw.y;
                float2 fa = __half22float2(ha);
                float2 fb2 = __half22float2(hb);
                v = make_float4(fa.x, fa.y, fb2.x, fb2.y);
            }
        }
        ((float4*)(xs + r * CINP))[q] = v;
    }
    __syncthreads();

    float d[2][4][4];
#pragma unroll
    for (int mt = 0; mt < 2; mt++)
#pragma unroll
        for (int nt = 0; nt < 4; nt++)
#pragma unroll
            for (int j = 0; j < 4; j++) d[mt][nt][j] = 0.0f;

    const float* xbase = xs + (tg * 32 + (lane >> 2)) * CINP + (lane & 3);
    const float* wfl = wf + nh * 256 + lane * 2;  // [ks][ntg][lane][2]; ntg = nh*4 + ntl

    for (int tap = 0; tap < 5; tap++) {
        const float* xtap = xbase + tap * CINP;
#pragma unroll
        for (int s = 0; s < S; s++) {
            const float* xp = xtap + s * 8;
            uint32_t a[2][4];
#pragma unroll
            for (int mt = 0; mt < 2; mt++) {
                const float* xm = xp + mt * 16 * CINP;
                a[mt][0] = __float_as_uint(xm[0]);
                a[mt][1] = __float_as_uint(xm[8 * CINP]);
                a[mt][2] = __float_as_uint(xm[4]);
                a[mt][3] = __float_as_uint(xm[8 * CINP + 4]);
            }
            const float* wr = wfl + (tap * S + s) * 512;
#pragma unroll
            for (int nt = 0; nt < 4; nt++) {
                uint2 bv = __ldg((const uint2*)(wr + nt * 64));
                mma8(d[0][nt], a[0], bv);
                mma8(d[1][nt], a[1], bv);
            }
        }
    }

    if (!FUSE3) {
        // store h1 as fp16 (exact for tf32-mantissa values in normal range)
#pragma unroll
        for (int mt = 0; mt < 2; mt++)
#pragma unroll
            for (int rh = 0; rh < 2; rh++) {
                int t = t0 + tg * 32 + mt * 16 + rh * 8 + (lane >> 2);
                __half* hb = g_h1 + ((size_t)b * TLEN + t) * 64;
#pragma unroll
                for (int nt = 0; nt < 4; nt++) {
                    int n = nh * 32 + nt * 8 + 2 * (lane & 3);
                    float va = gelu_exact(d[mt][nt][2 * rh + 0] + sb2[n]);
                    float vb = gelu_exact(d[mt][nt][2 * rh + 1] + sb2[n + 1]);
                    *(__half2*)(hb + n) = __floats2half2_rn(va, vb);
                }
            }
    } else {
        float part[2][2] = {{0.0f, 0.0f}, {0.0f, 0.0f}};
#pragma unroll
        for (int nt = 0; nt < 4; nt++)
#pragma unroll
            for (int j = 0; j < 2; j++) {
                int o = nh * 32 + nt * 8 + 2 * (lane & 3) + j;
                float wv = sw3s[o], bv = sb2[o];
#pragma unroll
                for (int mt = 0; mt < 2; mt++) {
                    part[mt][0] += wv * gelu_exact(d[mt][nt][j] + bv);
                    part[mt][1] += wv * gelu_exact(d[mt][nt][2 + j] + bv);
                }
            }
#pragma unroll
        for (int mt = 0; mt < 2; mt++)
#pragma unroll
            for (int rh = 0; rh < 2; rh++) {
                float v = part[mt][rh];
                v += __shfl_xor_sync(0xffffffffu, v, 1);
                v += __shfl_xor_sync(0xffffffffu, v, 2);
                if ((lane & 3) == 0)
                    pr[nh * 128 + tg * 32 + mt * 16 + rh * 8 + (lane >> 2)] = v;
            }
        __syncthreads();
        if (tid < 128) {
            int t = t0 + tid;
            float v = pr[tid] + pr[128 + tid] + b3[0];
            float m = amask[(size_t)b * TLEN + t];
            g_lr[(size_t)b * TLEN + t] = sigmoidf(v) * m;
        }
    }
}

// ---------------- kernel: smooth learned, combine, clip ----------------
__global__ void __launch_bounds__(256) k_final(const float* __restrict__ amask,
                                               float* __restrict__ out) {
    int b = blockIdx.y;
    int t = blockIdx.x * 256 + threadIdx.x;
    const float* lr = g_lr + (size_t)b * TLEN;
    float m = amask[(size_t)b * TLEN + t];
    float acc = 0.0f;
#pragma unroll
    for (int d = -2; d <= 2; d++) {
        int u = t + d;
        if (u >= 0 && u < TLEN) acc += lr[u];
    }
    float learned = fminf(fmaxf(acc * 0.2f * m, 0.0f), 1.0f);
    float r = g_rule[(size_t)b * TLEN + t];
    float o = 0.5f * r + 0.5f * learned;
    out[(size_t)b * TLEN + t] = fminf(fmaxf(o, 0.0f), 1.0f) * m;
}

// ---------------- launch: DAG with side-stream overlap (graph-capture safe) ----------
extern "C" void kernel_launch(void* const* d_in, const int* in_sizes, int n_in,
                              void* d_out, int out_size) {
    const float* traj = (const float*)d_in[0];
    const float* intervals = (const float*)d_in[1];
    const float* amask = (const float*)d_in[2];
    const float* obs = (const float*)d_in[3];
    const float* w1 = (const float*)d_in[4];
    const float* b1 = (const float*)d_in[5];
    const float* w2 = (const float*)d_in[6];
    const float* b2 = (const float*)d_in[7];
    const float* w3 = (const float*)d_in[8];
    const float* b3 = (const float*)d_in[9];
    float* out = (float*)d_out;

    const int SMEM_RULE = 3 * TLEN * 4;              // 49152
    const int SMEM_C1 = 132 * 20 * 4;                // 10560
    const int SMEM_C2 = 132 * 68 * 4;                // 35904 (4 CTAs/SM: 143.6 KB)

    cudaFuncSetAttribute(k_rule, cudaFuncAttributeMaxDynamicSharedMemorySize, SMEM_RULE);

    // one-time host-side handles (no device memory; identical work every call)
    static cudaStream_t s2 = nullptr;
    static cudaEvent_t evStart = nullptr, evFeat = nullptr, evPrep = nullptr,
                       evRule = nullptr;
    if (s2 == nullptr) {
        cudaStreamCreateWithFlags(&s2, cudaStreamNonBlocking);
        cudaEventCreateWithFlags(&evStart, cudaEventDisableTiming);
        cudaEventCreateWithFlags(&evFeat, cudaEventDisableTiming);
        cudaEventCreateWithFlags(&evPrep, cudaEventDisableTiming);
        cudaEventCreateWithFlags(&evRule, cudaEventDisableTiming);
    }
    cudaStream_t s0 = 0;  // origin (capture) stream

    // fork side stream
    cudaEventRecord(evStart, s0);
    cudaStreamWaitEvent(s2, evStart, 0);

    // s2: weight-fragment prep (independent of k_feat)
    k_prepw<<<50, 256, 0, s2>>>(w1, w2);
    cudaEventRecord(evPrep, s2);

    // s0: features
    k_feat<<<dim3(TLEN / 256, BATCH), 256, 0, s0>>>(traj, intervals, amask, obs);
    cudaEventRecord(evFeat, s0);

    // s2: rule scores depend only on k_feat -> overlap with conv1+conv2
    cudaStreamWaitEvent(s2, evFeat, 0);
    k_rule<<<BATCH, 1024, SMEM_RULE, s2>>>(amask);
    cudaEventRecord(evRule, s2);

    // s0: convs (conv1 needs featsA + wf1)
    cudaStreamWaitEvent(s0, evPrep, 0);
    conv_mma<16, false><<<dim3(TLEN / 128, BATCH), 256, SMEM_C1, s0>>>(b1, w3, b3, amask);
    conv_mma<64, true><<<dim3(TLEN / 128, BATCH), 256, SMEM_C2, s0>>>(b2, w3, b3, amask);

    // join and finalize
    cudaStreamWaitEvent(s0, evRule, 0);
    k_final<<<dim3(TLEN / 256, BATCH), 256, 0, s0>>>(amask, out);
}